// round 4
// baseline (speedup 1.0000x reference)
#include <cuda_runtime.h>
#include <math.h>
#include <stdint.h>

// Flash attention, tensor-core tf32 with PRE-SPLIT hi/lo operand tiles in smem.
// S=8192, D=128. out = softmax(q k^T / sqrt(D)) @ v
// CTA: 256 threads (8 warps), BM=64 query rows, loop over 128 K/V tiles (BN=64).
// All operand splits (x = tf32(x) + tf32(x - tf32(x))) happen once at tile load;
// inner loops are pure LDS + mma.sync.m16n8k8 (3 MMAs per split product).

namespace {
constexpr int S_TOTAL  = 8192;
constexpr int D_DIM    = 128;
constexpr int BM       = 64;
constexpr int BN       = 64;
constexpr int NTHREADS = 256;
constexpr int QK_STRIDE = 132;   // Qh/Ql/Kh/Kl row stride
constexpr int VS_STRIDE = 136;   // Vh/Vl row stride (conflict-free scalar frag reads)
constexpr int P_STRIDE  = 68;    // Ps row stride
constexpr int NTILES    = S_TOTAL / BN;

constexpr int OFF_QH    = 0;
constexpr int OFF_QL    = OFF_QH + BM * QK_STRIDE;
constexpr int OFF_KH    = OFF_QL + BM * QK_STRIDE;
constexpr int OFF_KL    = OFF_KH + BN * QK_STRIDE;
constexpr int OFF_VH    = OFF_KL + BN * QK_STRIDE;
constexpr int OFF_VL    = OFF_VH + BN * VS_STRIDE;
constexpr int OFF_P     = OFF_VL + BN * VS_STRIDE;
constexpr int OFF_RM    = OFF_P + BM * P_STRIDE;     // red max [64][2]
constexpr int OFF_RS    = OFF_RM + BM * 2;           // red sum [64][2]
constexpr int OFF_ROWM  = OFF_RS + BM * 2;
constexpr int OFF_ROWL  = OFF_ROWM + BM;
constexpr int OFF_ROWSC = OFF_ROWL + BM;
constexpr int SMEM_FLOATS = OFF_ROWSC + BM;          // 56000 floats = 224000 B
}  // namespace

__device__ __forceinline__ int perm8(int c) {
    // maps col c so that pairs (c, c+4) within an 8-block become adjacent
    return ((c & 3) << 1) | ((c >> 2) & 1);
}

__device__ __forceinline__ void split_tf32(float x, uint32_t& hi, uint32_t& lo) {
    uint32_t h;
    asm("cvt.rna.tf32.f32 %0, %1;" : "=r"(h) : "f"(x));
    float r = x - __uint_as_float(h);
    asm("cvt.rna.tf32.f32 %0, %1;" : "=r"(lo) : "f"(r));
    hi = h;
}

__device__ __forceinline__ void mma8(float* c,
                                     uint32_t a0, uint32_t a1, uint32_t a2, uint32_t a3,
                                     uint32_t b0, uint32_t b1) {
    asm volatile(
        "mma.sync.aligned.m16n8k8.row.col.f32.tf32.tf32.f32 "
        "{%0,%1,%2,%3}, {%4,%5,%6,%7}, {%8,%9}, {%0,%1,%2,%3};\n"
        : "+f"(c[0]), "+f"(c[1]), "+f"(c[2]), "+f"(c[3])
        : "r"(a0), "r"(a1), "r"(a2), "r"(a3), "r"(b0), "r"(b1));
}

// 3-term split MMA: C += Ahi*Bhi + Ahi*Blo + Alo*Bhi
__device__ __forceinline__ void mma8_split(float* c,
                                           const uint32_t ah[4], const uint32_t al[4],
                                           uint32_t bh0, uint32_t bh1,
                                           uint32_t bl0, uint32_t bl1) {
    mma8(c, ah[0], ah[1], ah[2], ah[3], bh0, bh1);
    mma8(c, ah[0], ah[1], ah[2], ah[3], bl0, bl1);
    mma8(c, al[0], al[1], al[2], al[3], bh0, bh1);
}

// split a float4 and store hi/lo with the perm8 column mapping
__device__ __forceinline__ void store_perm4_split(float* hrow, float* lrow, int c4, float4 v) {
    int blk = (c4 * 4) & ~7;
    int lo4 = (c4 & 1) * 4;
    uint32_t h, l;
    split_tf32(v.x, h, l);
    hrow[blk + perm8(lo4 + 0)] = __uint_as_float(h);
    lrow[blk + perm8(lo4 + 0)] = __uint_as_float(l);
    split_tf32(v.y, h, l);
    hrow[blk + perm8(lo4 + 1)] = __uint_as_float(h);
    lrow[blk + perm8(lo4 + 1)] = __uint_as_float(l);
    split_tf32(v.z, h, l);
    hrow[blk + perm8(lo4 + 2)] = __uint_as_float(h);
    lrow[blk + perm8(lo4 + 2)] = __uint_as_float(l);
    split_tf32(v.w, h, l);
    hrow[blk + perm8(lo4 + 3)] = __uint_as_float(h);
    lrow[blk + perm8(lo4 + 3)] = __uint_as_float(l);
}

__global__ __launch_bounds__(NTHREADS, 1)
void fa_tf32_kernel(const float* __restrict__ gq,
                    const float* __restrict__ gk,
                    const float* __restrict__ gv,
                    float* __restrict__ gout) {
    extern __shared__ float sm[];
    float* Qh     = sm + OFF_QH;
    float* Ql     = sm + OFF_QL;
    float* Kh     = sm + OFF_KH;
    float* Kl     = sm + OFF_KL;
    float* Vh     = sm + OFF_VH;
    float* Vl     = sm + OFF_VL;
    float* Ps     = sm + OFF_P;
    float* red_m  = sm + OFF_RM;
    float* red_s  = sm + OFF_RS;
    float* row_m  = sm + OFF_ROWM;
    float* row_l  = sm + OFF_ROWL;
    float* row_sc = sm + OFF_ROWSC;

    const int tid  = threadIdx.x;
    const int lane = tid & 31;
    const int warp = tid >> 5;
    const int wr   = warp & 3;       // warp row group: rows [wr*16, wr*16+16)
    const int wc   = warp >> 2;      // warp col half
    const int lq   = lane & 3;       // thread-in-group (k index)
    const int lr   = lane >> 2;      // group id (row 0..7)
    const int r0   = wr * 16 + lr;   // rows r0 and r0+8 owned by this thread

    const int qbase = blockIdx.x * BM;
    const float4* gq4 = reinterpret_cast<const float4*>(gq);
    const float4* gk4 = reinterpret_cast<const float4*>(gk);
    const float4* gv4 = reinterpret_cast<const float4*>(gv);

    // ---- load + split Q tile once ----
#pragma unroll
    for (int it = 0; it < (BM * D_DIM / 4) / NTHREADS; ++it) {
        int idx = it * NTHREADS + tid;
        int row = idx >> 5;
        int c4  = idx & 31;
        float4 v = gq4[(size_t)(qbase + row) * (D_DIM / 4) + c4];
        store_perm4_split(&Qh[row * QK_STRIDE], &Ql[row * QK_STRIDE], c4, v);
    }
    if (tid < BM) { row_m[tid] = -INFINITY; row_l[tid] = 0.0f; }

    float acc_o[8][4];
#pragma unroll
    for (int n = 0; n < 8; ++n)
#pragma unroll
        for (int j = 0; j < 4; ++j) acc_o[n][j] = 0.0f;

    const float sm_scale = 0.08838834764831845f;  // 1/sqrt(128)

    for (int t = 0; t < NTILES; ++t) {
        __syncthreads();  // protect tiles from previous iteration readers
        const int kb = t * BN;

        // ---- load + split K (perm cols) and V (straight rows) ----
#pragma unroll
        for (int it = 0; it < (BN * D_DIM / 4) / NTHREADS; ++it) {
            int idx = it * NTHREADS + tid;
            int row = idx >> 5;
            int c4  = idx & 31;
            float4 v = gk4[(size_t)(kb + row) * (D_DIM / 4) + c4];
            store_perm4_split(&Kh[row * QK_STRIDE], &Kl[row * QK_STRIDE], c4, v);
        }
#pragma unroll
        for (int it = 0; it < (BN * D_DIM / 4) / NTHREADS; ++it) {
            int idx = it * NTHREADS + tid;
            int s   = idx >> 5;
            int c4  = idx & 31;
            float4 v = gv4[(size_t)(kb + s) * (D_DIM / 4) + c4];
            float4 hv, lv;
            uint32_t h, l;
            split_tf32(v.x, h, l); hv.x = __uint_as_float(h); lv.x = __uint_as_float(l);
            split_tf32(v.y, h, l); hv.y = __uint_as_float(h); lv.y = __uint_as_float(l);
            split_tf32(v.z, h, l); hv.z = __uint_as_float(h); lv.z = __uint_as_float(l);
            split_tf32(v.w, h, l); hv.w = __uint_as_float(h); lv.w = __uint_as_float(l);
            *reinterpret_cast<float4*>(&Vh[s * VS_STRIDE + c4 * 4]) = hv;
            *reinterpret_cast<float4*>(&Vl[s * VS_STRIDE + c4 * 4]) = lv;
        }
        __syncthreads();

        // ---- S = Q K^T : pure LDS + MMA ----
        float sc[4][4];
#pragma unroll
        for (int n = 0; n < 4; ++n)
#pragma unroll
            for (int j = 0; j < 4; ++j) sc[n][j] = 0.0f;

#pragma unroll
        for (int ks = 0; ks < D_DIM / 8; ++ks) {
            const int k0 = ks * 8;
            float2 qah = *reinterpret_cast<const float2*>(&Qh[r0 * QK_STRIDE + k0 + 2 * lq]);
            float2 qbh = *reinterpret_cast<const float2*>(&Qh[(r0 + 8) * QK_STRIDE + k0 + 2 * lq]);
            float2 qal = *reinterpret_cast<const float2*>(&Ql[r0 * QK_STRIDE + k0 + 2 * lq]);
            float2 qbl = *reinterpret_cast<const float2*>(&Ql[(r0 + 8) * QK_STRIDE + k0 + 2 * lq]);
            uint32_t ah[4] = { __float_as_uint(qah.x), __float_as_uint(qbh.x),
                               __float_as_uint(qah.y), __float_as_uint(qbh.y) };
            uint32_t al[4] = { __float_as_uint(qal.x), __float_as_uint(qbl.x),
                               __float_as_uint(qal.y), __float_as_uint(qbl.y) };
#pragma unroll
            for (int nt = 0; nt < 4; ++nt) {
                const int n0 = wc * 32 + nt * 8;
                float2 kvh = *reinterpret_cast<const float2*>(&Kh[(n0 + lr) * QK_STRIDE + k0 + 2 * lq]);
                float2 kvl = *reinterpret_cast<const float2*>(&Kl[(n0 + lr) * QK_STRIDE + k0 + 2 * lq]);
                mma8_split(sc[nt], ah, al,
                           __float_as_uint(kvh.x), __float_as_uint(kvh.y),
                           __float_as_uint(kvl.x), __float_as_uint(kvl.y));
            }
        }

        // ---- softmax stats ----
        float mr = -INFINITY, mr8 = -INFINITY;
#pragma unroll
        for (int nt = 0; nt < 4; ++nt) {
            sc[nt][0] *= sm_scale; sc[nt][1] *= sm_scale;
            sc[nt][2] *= sm_scale; sc[nt][3] *= sm_scale;
            mr  = fmaxf(mr,  fmaxf(sc[nt][0], sc[nt][1]));
            mr8 = fmaxf(mr8, fmaxf(sc[nt][2], sc[nt][3]));
        }
        mr  = fmaxf(mr,  __shfl_xor_sync(0xffffffffu, mr, 1));
        mr  = fmaxf(mr,  __shfl_xor_sync(0xffffffffu, mr, 2));
        mr8 = fmaxf(mr8, __shfl_xor_sync(0xffffffffu, mr8, 1));
        mr8 = fmaxf(mr8, __shfl_xor_sync(0xffffffffu, mr8, 2));
        if (lq == 0) {
            red_m[r0 * 2 + wc]       = mr;
            red_m[(r0 + 8) * 2 + wc] = mr8;
        }
        __syncthreads();

        if (tid < BM) {
            float mo = row_m[tid];
            float mn = fmaxf(mo, fmaxf(red_m[tid * 2], red_m[tid * 2 + 1]));
            row_m[tid]  = mn;
            row_sc[tid] = __expf(mo - mn);  // 0 on first tile
        }
        __syncthreads();

        // ---- exp, write P (perm cols), partial row sums ----
        const float mrow  = row_m[r0];
        const float mrow8 = row_m[r0 + 8];
        float s_r = 0.0f, s_r8 = 0.0f;
        const int o0 = perm8(2 * lq);
        const int o1 = perm8(2 * lq + 1);
#pragma unroll
        for (int nt = 0; nt < 4; ++nt) {
            const int cb = wc * 32 + nt * 8;
            float p00 = __expf(sc[nt][0] - mrow);
            float p01 = __expf(sc[nt][1] - mrow);
            float p10 = __expf(sc[nt][2] - mrow8);
            float p11 = __expf(sc[nt][3] - mrow8);
            s_r  += p00 + p01;
            s_r8 += p10 + p11;
            Ps[r0 * P_STRIDE + cb + o0]       = p00;
            Ps[r0 * P_STRIDE + cb + o1]       = p01;
            Ps[(r0 + 8) * P_STRIDE + cb + o0] = p10;
            Ps[(r0 + 8) * P_STRIDE + cb + o1] = p11;
        }
        s_r  += __shfl_xor_sync(0xffffffffu, s_r, 1);
        s_r  += __shfl_xor_sync(0xffffffffu, s_r, 2);
        s_r8 += __shfl_xor_sync(0xffffffffu, s_r8, 1);
        s_r8 += __shfl_xor_sync(0xffffffffu, s_r8, 2);
        if (lq == 0) {
            red_s[r0 * 2 + wc]       = s_r;
            red_s[(r0 + 8) * 2 + wc] = s_r8;
        }

        // rescale O accumulators
        const float f0 = row_sc[r0];
        const float f1 = row_sc[r0 + 8];
#pragma unroll
        for (int nt = 0; nt < 8; ++nt) {
            acc_o[nt][0] *= f0; acc_o[nt][1] *= f0;
            acc_o[nt][2] *= f1; acc_o[nt][3] *= f1;
        }
        __syncthreads();

        if (tid < BM)
            row_l[tid] = row_l[tid] * row_sc[tid] + red_s[tid * 2] + red_s[tid * 2 + 1];

        // ---- O += P V : A split in registers, B pre-split in smem ----
#pragma unroll
        for (int ks = 0; ks < BN / 8; ++ks) {
            const int k0 = ks * 8;
            float2 pa = *reinterpret_cast<const float2*>(&Ps[r0 * P_STRIDE + k0 + 2 * lq]);
            float2 pb = *reinterpret_cast<const float2*>(&Ps[(r0 + 8) * P_STRIDE + k0 + 2 * lq]);
            uint32_t ah[4], al[4];
            split_tf32(pa.x, ah[0], al[0]);
            split_tf32(pb.x, ah[1], al[1]);
            split_tf32(pa.y, ah[2], al[2]);
            split_tf32(pb.y, ah[3], al[3]);
#pragma unroll
            for (int nt = 0; nt < 8; ++nt) {
                const int n0 = wc * 64 + nt * 8;
                // bank = (8*lq + lr) across warp: conflict-free scalar reads
                float v0h = Vh[(k0 + lq) * VS_STRIDE + n0 + lr];
                float v1h = Vh[(k0 + lq + 4) * VS_STRIDE + n0 + lr];
                float v0l = Vl[(k0 + lq) * VS_STRIDE + n0 + lr];
                float v1l = Vl[(k0 + lq + 4) * VS_STRIDE + n0 + lr];
                mma8_split(acc_o[nt], ah, al,
                           __float_as_uint(v0h), __float_as_uint(v1h),
                           __float_as_uint(v0l), __float_as_uint(v1l));
            }
        }
    }

    __syncthreads();

    // ---- normalize + store ----
    const float inv0 = 1.0f / row_l[r0];
    const float inv1 = 1.0f / row_l[r0 + 8];
#pragma unroll
    for (int nt = 0; nt < 8; ++nt) {
        const int d0 = wc * 64 + nt * 8 + 2 * lq;
        float2 oa, ob;
        oa.x = acc_o[nt][0] * inv0; oa.y = acc_o[nt][1] * inv0;
        ob.x = acc_o[nt][2] * inv1; ob.y = acc_o[nt][3] * inv1;
        *reinterpret_cast<float2*>(&gout[(size_t)(qbase + r0) * D_DIM + d0])     = oa;
        *reinterpret_cast<float2*>(&gout[(size_t)(qbase + r0 + 8) * D_DIM + d0]) = ob;
    }
}

extern "C" void kernel_launch(void* const* d_in, const int* in_sizes, int n_in,
                              void* d_out, int out_size) {
    const float* q = (const float*)d_in[0];
    const float* k = (const float*)d_in[1];
    const float* v = (const float*)d_in[2];
    float* out = (float*)d_out;
    (void)in_sizes; (void)n_in; (void)out_size;

    const int smem_bytes = SMEM_FLOATS * (int)sizeof(float);  // 224000 B
    cudaFuncSetAttribute(fa_tf32_kernel,
                         cudaFuncAttributeMaxDynamicSharedMemorySize, smem_bytes);
    fa_tf32_kernel<<<S_TOTAL / BM, NTHREADS, smem_bytes>>>(q, k, v, out);
}

// round 5
// speedup vs baseline: 1.2197x; 1.2197x over previous
#include <cuda_runtime.h>
#include <math.h>
#include <stdint.h>

// Flash attention, tensor-core tf32.
// QK^T: full 3-term hi/lo split (pre-split Qh/Ql once, Kh/Kl per tile)  -> score err ~1e-7
// P@V : plain tf32 (V rounded at load, P rounded in-register)           -> ~3e-4 rel err, gate is 1e-3
// S=8192, D=128. CTA: 256 threads (8 warps), BM=64 rows, 128 tiles of BN=64.

namespace {
constexpr int S_TOTAL  = 8192;
constexpr int D_DIM    = 128;
constexpr int BM       = 64;
constexpr int BN       = 64;
constexpr int NTHREADS = 256;
constexpr int QK_STRIDE = 132;   // Qh/Ql/Kh/Kl row stride
constexpr int VS_STRIDE = 136;   // Vh row stride (conflict-free scalar frag reads)
constexpr int P_STRIDE  = 68;    // Ps row stride
constexpr int NTILES    = S_TOTAL / BN;

constexpr int OFF_QH    = 0;
constexpr int OFF_QL    = OFF_QH + BM * QK_STRIDE;
constexpr int OFF_KH    = OFF_QL + BM * QK_STRIDE;
constexpr int OFF_KL    = OFF_KH + BN * QK_STRIDE;
constexpr int OFF_VH    = OFF_KL + BN * QK_STRIDE;
constexpr int OFF_P     = OFF_VH + BN * VS_STRIDE;
constexpr int OFF_RM    = OFF_P + BM * P_STRIDE;     // red max [64][2]
constexpr int OFF_RS    = OFF_RM + BM * 2;           // red sum [64][2]
constexpr int OFF_ROWM  = OFF_RS + BM * 2;
constexpr int OFF_ROWL  = OFF_ROWM + BM;
constexpr int OFF_ROWSC = OFF_ROWL + BM;
constexpr int SMEM_FLOATS = OFF_ROWSC + BM;          // 47296 floats = 189184 B
}  // namespace

__device__ __forceinline__ int perm8(int c) {
    // maps col c so that pairs (c, c+4) within an 8-block become adjacent
    return ((c & 3) << 1) | ((c >> 2) & 1);
}

__device__ __forceinline__ void split_tf32(float x, uint32_t& hi, uint32_t& lo) {
    uint32_t h;
    asm("cvt.rna.tf32.f32 %0, %1;" : "=r"(h) : "f"(x));
    float r = x - __uint_as_float(h);
    asm("cvt.rna.tf32.f32 %0, %1;" : "=r"(lo) : "f"(r));
    hi = h;
}

__device__ __forceinline__ uint32_t tf32_rna(float x) {
    uint32_t h;
    asm("cvt.rna.tf32.f32 %0, %1;" : "=r"(h) : "f"(x));
    return h;
}

__device__ __forceinline__ void mma8(float* c,
                                     uint32_t a0, uint32_t a1, uint32_t a2, uint32_t a3,
                                     uint32_t b0, uint32_t b1) {
    asm volatile(
        "mma.sync.aligned.m16n8k8.row.col.f32.tf32.tf32.f32 "
        "{%0,%1,%2,%3}, {%4,%5,%6,%7}, {%8,%9}, {%0,%1,%2,%3};\n"
        : "+f"(c[0]), "+f"(c[1]), "+f"(c[2]), "+f"(c[3])
        : "r"(a0), "r"(a1), "r"(a2), "r"(a3), "r"(b0), "r"(b1));
}

// 3-term split MMA: C += Ahi*Bhi + Ahi*Blo + Alo*Bhi
__device__ __forceinline__ void mma8_split(float* c,
                                           const uint32_t ah[4], const uint32_t al[4],
                                           uint32_t bh0, uint32_t bh1,
                                           uint32_t bl0, uint32_t bl1) {
    mma8(c, ah[0], ah[1], ah[2], ah[3], bh0, bh1);
    mma8(c, ah[0], ah[1], ah[2], ah[3], bl0, bl1);
    mma8(c, al[0], al[1], al[2], al[3], bh0, bh1);
}

// split a float4 and store hi/lo with the perm8 column mapping
__device__ __forceinline__ void store_perm4_split(float* hrow, float* lrow, int c4, float4 v) {
    int blk = (c4 * 4) & ~7;
    int lo4 = (c4 & 1) * 4;
    uint32_t h, l;
    split_tf32(v.x, h, l);
    hrow[blk + perm8(lo4 + 0)] = __uint_as_float(h);
    lrow[blk + perm8(lo4 + 0)] = __uint_as_float(l);
    split_tf32(v.y, h, l);
    hrow[blk + perm8(lo4 + 1)] = __uint_as_float(h);
    lrow[blk + perm8(lo4 + 1)] = __uint_as_float(l);
    split_tf32(v.z, h, l);
    hrow[blk + perm8(lo4 + 2)] = __uint_as_float(h);
    lrow[blk + perm8(lo4 + 2)] = __uint_as_float(l);
    split_tf32(v.w, h, l);
    hrow[blk + perm8(lo4 + 3)] = __uint_as_float(h);
    lrow[blk + perm8(lo4 + 3)] = __uint_as_float(l);
}

__global__ __launch_bounds__(NTHREADS, 1)
void fa_tf32_kernel(const float* __restrict__ gq,
                    const float* __restrict__ gk,
                    const float* __restrict__ gv,
                    float* __restrict__ gout) {
    extern __shared__ float sm[];
    float* Qh     = sm + OFF_QH;
    float* Ql     = sm + OFF_QL;
    float* Kh     = sm + OFF_KH;
    float* Kl     = sm + OFF_KL;
    float* Vh     = sm + OFF_VH;
    float* Ps     = sm + OFF_P;
    float* red_m  = sm + OFF_RM;
    float* red_s  = sm + OFF_RS;
    float* row_m  = sm + OFF_ROWM;
    float* row_l  = sm + OFF_ROWL;
    float* row_sc = sm + OFF_ROWSC;

    const int tid  = threadIdx.x;
    const int lane = tid & 31;
    const int warp = tid >> 5;
    const int wr   = warp & 3;       // warp row group: rows [wr*16, wr*16+16)
    const int wc   = warp >> 2;      // warp col half
    const int lq   = lane & 3;       // thread-in-group (k index)
    const int lr   = lane >> 2;      // group id (row 0..7)
    const int r0   = wr * 16 + lr;   // rows r0 and r0+8 owned by this thread

    const int qbase = blockIdx.x * BM;
    const float4* gq4 = reinterpret_cast<const float4*>(gq);
    const float4* gk4 = reinterpret_cast<const float4*>(gk);
    const float4* gv4 = reinterpret_cast<const float4*>(gv);

    // ---- load + split Q tile once ----
#pragma unroll
    for (int it = 0; it < (BM * D_DIM / 4) / NTHREADS; ++it) {
        int idx = it * NTHREADS + tid;
        int row = idx >> 5;
        int c4  = idx & 31;
        float4 v = gq4[(size_t)(qbase + row) * (D_DIM / 4) + c4];
        store_perm4_split(&Qh[row * QK_STRIDE], &Ql[row * QK_STRIDE], c4, v);
    }
    if (tid < BM) { row_m[tid] = -INFINITY; row_l[tid] = 0.0f; }

    float acc_o[8][4];
#pragma unroll
    for (int n = 0; n < 8; ++n)
#pragma unroll
        for (int j = 0; j < 4; ++j) acc_o[n][j] = 0.0f;

    const float sm_scale = 0.08838834764831845f;  // 1/sqrt(128)

    for (int t = 0; t < NTILES; ++t) {
        __syncthreads();  // protect tiles from previous iteration readers
        const int kb = t * BN;

        // ---- load + split K (perm cols); load V (tf32-rounded, straight rows) ----
#pragma unroll
        for (int it = 0; it < (BN * D_DIM / 4) / NTHREADS; ++it) {
            int idx = it * NTHREADS + tid;
            int row = idx >> 5;
            int c4  = idx & 31;
            float4 v = gk4[(size_t)(kb + row) * (D_DIM / 4) + c4];
            store_perm4_split(&Kh[row * QK_STRIDE], &Kl[row * QK_STRIDE], c4, v);
        }
#pragma unroll
        for (int it = 0; it < (BN * D_DIM / 4) / NTHREADS; ++it) {
            int idx = it * NTHREADS + tid;
            int s   = idx >> 5;
            int c4  = idx & 31;
            float4 v = gv4[(size_t)(kb + s) * (D_DIM / 4) + c4];
            float4 hv;
            hv.x = __uint_as_float(tf32_rna(v.x));
            hv.y = __uint_as_float(tf32_rna(v.y));
            hv.z = __uint_as_float(tf32_rna(v.z));
            hv.w = __uint_as_float(tf32_rna(v.w));
            *reinterpret_cast<float4*>(&Vh[s * VS_STRIDE + c4 * 4]) = hv;
        }
        __syncthreads();

        // ---- S = Q K^T : pure LDS + MMA (3-term split) ----
        float sc[4][4];
#pragma unroll
        for (int n = 0; n < 4; ++n)
#pragma unroll
            for (int j = 0; j < 4; ++j) sc[n][j] = 0.0f;

#pragma unroll
        for (int ks = 0; ks < D_DIM / 8; ++ks) {
            const int k0 = ks * 8;
            float2 qah = *reinterpret_cast<const float2*>(&Qh[r0 * QK_STRIDE + k0 + 2 * lq]);
            float2 qbh = *reinterpret_cast<const float2*>(&Qh[(r0 + 8) * QK_STRIDE + k0 + 2 * lq]);
            float2 qal = *reinterpret_cast<const float2*>(&Ql[r0 * QK_STRIDE + k0 + 2 * lq]);
            float2 qbl = *reinterpret_cast<const float2*>(&Ql[(r0 + 8) * QK_STRIDE + k0 + 2 * lq]);
            uint32_t ah[4] = { __float_as_uint(qah.x), __float_as_uint(qbh.x),
                               __float_as_uint(qah.y), __float_as_uint(qbh.y) };
            uint32_t al[4] = { __float_as_uint(qal.x), __float_as_uint(qbl.x),
                               __float_as_uint(qal.y), __float_as_uint(qbl.y) };
#pragma unroll
            for (int nt = 0; nt < 4; ++nt) {
                const int n0 = wc * 32 + nt * 8;
                float2 kvh = *reinterpret_cast<const float2*>(&Kh[(n0 + lr) * QK_STRIDE + k0 + 2 * lq]);
                float2 kvl = *reinterpret_cast<const float2*>(&Kl[(n0 + lr) * QK_STRIDE + k0 + 2 * lq]);
                mma8_split(sc[nt], ah, al,
                           __float_as_uint(kvh.x), __float_as_uint(kvh.y),
                           __float_as_uint(kvl.x), __float_as_uint(kvl.y));
            }
        }

        // ---- softmax stats ----
        float mr = -INFINITY, mr8 = -INFINITY;
#pragma unroll
        for (int nt = 0; nt < 4; ++nt) {
            sc[nt][0] *= sm_scale; sc[nt][1] *= sm_scale;
            sc[nt][2] *= sm_scale; sc[nt][3] *= sm_scale;
            mr  = fmaxf(mr,  fmaxf(sc[nt][0], sc[nt][1]));
            mr8 = fmaxf(mr8, fmaxf(sc[nt][2], sc[nt][3]));
        }
        mr  = fmaxf(mr,  __shfl_xor_sync(0xffffffffu, mr, 1));
        mr  = fmaxf(mr,  __shfl_xor_sync(0xffffffffu, mr, 2));
        mr8 = fmaxf(mr8, __shfl_xor_sync(0xffffffffu, mr8, 1));
        mr8 = fmaxf(mr8, __shfl_xor_sync(0xffffffffu, mr8, 2));
        if (lq == 0) {
            red_m[r0 * 2 + wc]       = mr;
            red_m[(r0 + 8) * 2 + wc] = mr8;
        }
        __syncthreads();

        if (tid < BM) {
            float mo = row_m[tid];
            float mn = fmaxf(mo, fmaxf(red_m[tid * 2], red_m[tid * 2 + 1]));
            row_m[tid]  = mn;
            row_sc[tid] = __expf(mo - mn);  // 0 on first tile
        }
        __syncthreads();

        // ---- exp, write P (perm cols), partial row sums ----
        const float mrow  = row_m[r0];
        const float mrow8 = row_m[r0 + 8];
        float s_r = 0.0f, s_r8 = 0.0f;
        const int o0 = perm8(2 * lq);
        const int o1 = perm8(2 * lq + 1);
#pragma unroll
        for (int nt = 0; nt < 4; ++nt) {
            const int cb = wc * 32 + nt * 8;
            float p00 = __expf(sc[nt][0] - mrow);
            float p01 = __expf(sc[nt][1] - mrow);
            float p10 = __expf(sc[nt][2] - mrow8);
            float p11 = __expf(sc[nt][3] - mrow8);
            s_r  += p00 + p01;
            s_r8 += p10 + p11;
            Ps[r0 * P_STRIDE + cb + o0]       = p00;
            Ps[r0 * P_STRIDE + cb + o1]       = p01;
            Ps[(r0 + 8) * P_STRIDE + cb + o0] = p10;
            Ps[(r0 + 8) * P_STRIDE + cb + o1] = p11;
        }
        s_r  += __shfl_xor_sync(0xffffffffu, s_r, 1);
        s_r  += __shfl_xor_sync(0xffffffffu, s_r, 2);
        s_r8 += __shfl_xor_sync(0xffffffffu, s_r8, 1);
        s_r8 += __shfl_xor_sync(0xffffffffu, s_r8, 2);
        if (lq == 0) {
            red_s[r0 * 2 + wc]       = s_r;
            red_s[(r0 + 8) * 2 + wc] = s_r8;
        }

        // rescale O accumulators
        const float f0 = row_sc[r0];
        const float f1 = row_sc[r0 + 8];
#pragma unroll
        for (int nt = 0; nt < 8; ++nt) {
            acc_o[nt][0] *= f0; acc_o[nt][1] *= f0;
            acc_o[nt][2] *= f1; acc_o[nt][3] *= f1;
        }
        __syncthreads();

        if (tid < BM)
            row_l[tid] = row_l[tid] * row_sc[tid] + red_s[tid * 2] + red_s[tid * 2 + 1];

        // ---- O += P V : plain tf32 (1 MMA per product) ----
#pragma unroll
        for (int ks = 0; ks < BN / 8; ++ks) {
            const int k0 = ks * 8;
            float2 pa = *reinterpret_cast<const float2*>(&Ps[r0 * P_STRIDE + k0 + 2 * lq]);
            float2 pb = *reinterpret_cast<const float2*>(&Ps[(r0 + 8) * P_STRIDE + k0 + 2 * lq]);
            uint32_t ah0 = tf32_rna(pa.x);
            uint32_t ah1 = tf32_rna(pb.x);
            uint32_t ah2 = tf32_rna(pa.y);
            uint32_t ah3 = tf32_rna(pb.y);
#pragma unroll
            for (int nt = 0; nt < 8; ++nt) {
                const int n0 = wc * 64 + nt * 8;
                // bank = (8*lq + lr) across warp: conflict-free scalar reads
                float v0h = Vh[(k0 + lq) * VS_STRIDE + n0 + lr];
                float v1h = Vh[(k0 + lq + 4) * VS_STRIDE + n0 + lr];
                mma8(acc_o[nt], ah0, ah1, ah2, ah3,
                     __float_as_uint(v0h), __float_as_uint(v1h));
            }
        }
    }

    __syncthreads();

    // ---- normalize + store ----
    const float inv0 = 1.0f / row_l[r0];
    const float inv1 = 1.0f / row_l[r0 + 8];
#pragma unroll
    for (int nt = 0; nt < 8; ++nt) {
        const int d0 = wc * 64 + nt * 8 + 2 * lq;
        float2 oa, ob;
        oa.x = acc_o[nt][0] * inv0; oa.y = acc_o[nt][1] * inv0;
        ob.x = acc_o[nt][2] * inv1; ob.y = acc_o[nt][3] * inv1;
        *reinterpret_cast<float2*>(&gout[(size_t)(qbase + r0) * D_DIM + d0])     = oa;
        *reinterpret_cast<float2*>(&gout[(size_t)(qbase + r0 + 8) * D_DIM + d0]) = ob;
    }
}

extern "C" void kernel_launch(void* const* d_in, const int* in_sizes, int n_in,
                              void* d_out, int out_size) {
    const float* q = (const float*)d_in[0];
    const float* k = (const float*)d_in[1];
    const float* v = (const float*)d_in[2];
    float* out = (float*)d_out;
    (void)in_sizes; (void)n_in; (void)out_size;

    const int smem_bytes = SMEM_FLOATS * (int)sizeof(float);  // 189184 B
    cudaFuncSetAttribute(fa_tf32_kernel,
                         cudaFuncAttributeMaxDynamicSharedMemorySize, smem_bytes);
    fa_tf32_kernel<<<S_TOTAL / BM, NTHREADS, smem_bytes>>>(q, k, v, out);
}